// round 14
// baseline (speedup 1.0000x reference)
#include <cuda_runtime.h>

// ContrastiveLoss (discriminative loss), fixed shapes:
//   input_:  (4, 32, 512, 512) float32, channel-major
//   target:  (4, 1, 512, 512)  int32, labels in [0, 100)
// Output: scalar float32.

#define BB 4
#define CC 32
#define HW 262144
#define NI 100
#define NBLK 256              // pass1 blocks per batch
#define PSZ 3300              // partial: 100*32 sums + 100 counts
#define MEANSZ 3536           // 32*104 meansT + 104 msq + 104 invc
#define MP 104                // transposed means pitch
#define STREAM 128            // k_var streaming blocks per batch
#define TP 36                 // stage tile pitch (px dim), 16B-aligned rows
#define DVAR 0.75f
#define REP 4.0f              // 2 * DELTA_DIST

__device__ float g_part[BB * NBLK * PSZ];   // 13.5 MB raw per-block tables
__device__ float g_mean[BB * MEANSZ];       // meansT + ||m||^2 + 1/cnt

// ---------------------------------------------------------------------------
// Pass 1: per-label sums + counts. Conflict-free block-shared ATOMS table
// (T[l*32+lane], lane=channel via broadcast labels -> bank=lane). Staging is
// vectorized ([c][px] tile, pitch 36) AND register double-buffered: chunk
// ch+1's 8 LDG.128 are issued before chunk ch's consume, so DRAM loads stay
// in flight through the ATOMS phase instead of serializing behind it.
// Grid (256, 4), block 128 (4 warps), warp owns 256 px in 8 chunks of 32.
__global__ void __launch_bounds__(128) k_pass1(const float* __restrict__ in,
                                               const int* __restrict__ tgt) {
    __shared__ float T[NI * 32];                        // 12.8 KB
    __shared__ float Cn[NI];                            // 400 B
    __shared__ __align__(16) float tile[4][CC * TP];    // 18.4 KB
    __shared__ __align__(16) int   lab[4][32];

    const int b    = blockIdx.y;
    const int tid  = threadIdx.x;
    const int warp = tid >> 5;
    const int lane = tid & 31;
    float* TL = tile[warp];
    int*   L  = lab[warp];

    for (int i = tid; i < NI * 32; i += 128) T[i] = 0.0f;
    if (tid < NI) Cn[tid] = 0.0f;
    __syncthreads();

    const int*   tb  = tgt + (size_t)b * HW;
    const float* inb = in  + (size_t)b * CC * HW;
    const int base = blockIdx.x * 1024 + warp * 256;

    const int cg = lane >> 3;          // channel sub-group 0..3
    const int j4 = 4 * (lane & 7);     // pixel quad 0,4,...,28

    // prefetch chunk 0 into registers
    float4 buf[8];
#pragma unroll
    for (int i = 0; i < 8; ++i)
        buf[i] = *(const float4*)(inb + (size_t)(i * 4 + cg) * HW + base + j4);

    for (int ch = 0; ch < 8; ++ch) {
        const int p0 = base + ch * 32;
        if (lane < 8) ((int4*)L)[lane] = ((const int4*)(tb + p0))[lane];

        // stage current chunk from registers (8 STS.128)
#pragma unroll
        for (int i = 0; i < 8; ++i)
            *(float4*)(TL + (i * 4 + cg) * TP + j4) = buf[i];
        __syncwarp();

        // prefetch next chunk: LDGs overlap the consume phase below
        if (ch < 7) {
            const int p1 = p0 + 32;
#pragma unroll
            for (int i = 0; i < 8; ++i)
                buf[i] = *(const float4*)(inb + (size_t)(i * 4 + cg) * HW + p1 + j4);
        }

        // counts: one leader atomic per distinct label in this chunk
        {
            const int l = L[lane];
            const unsigned grp = __match_any_sync(0xffffffffu, l);
            if (lane == __ffs(grp) - 1)
                atomicAdd(&Cn[l], (float)__popc(grp));
        }

        // consume: per 4-px group: broadcast label LDS.128 + LDS.128 of
        // 4 px (channel = lane) + 4 conflict-free ATOMS
#pragma unroll
        for (int g = 0; g < 8; ++g) {
            const int4   Lg = *(const int4*)(L + g * 4);
            const float4 v  = *(const float4*)(TL + lane * TP + g * 4);
            atomicAdd(&T[Lg.x * 32 + lane], v.x);
            atomicAdd(&T[Lg.y * 32 + lane], v.y);
            atomicAdd(&T[Lg.z * 32 + lane], v.z);
            atomicAdd(&T[Lg.w * 32 + lane], v.w);
        }
        __syncwarp();
    }
    __syncthreads();

    // flush raw partials (plain coalesced stores, no global atomics)
    float* dst = g_part + (size_t)(b * NBLK + blockIdx.x) * PSZ;
    for (int i = tid; i < NI * 32; i += 128) dst[i] = T[i];
    if (tid < NI) dst[NI * 32 + tid] = Cn[tid];
}

// ---------------------------------------------------------------------------
// Reduce 256 partials/batch -> transposed means + ||m||^2 + 1/cnt.
// Grid (100, 4) [block = one label], 160 threads. Also zeroes out[0].
__global__ void __launch_bounds__(160) k_reduce(float* __restrict__ out) {
    __shared__ float ssum[4][32];
    __shared__ float scnt;

    const int b = blockIdx.y, l = blockIdx.x;
    const int t = threadIdx.x, g = t >> 5, lane = t & 31;
    const float* base = g_part + (size_t)b * NBLK * PSZ;

    if (g < 4) {
        float s = 0.0f;
        const float* p = base + l * 32 + lane;
#pragma unroll 8
        for (int k = g * 64; k < g * 64 + 64; ++k) s += p[(size_t)k * PSZ];
        ssum[g][lane] = s;
    } else {
        float s = 0.0f;
        const float* p = base + NI * 32 + l;
#pragma unroll
        for (int i = 0; i < 8; ++i) s += p[(size_t)(lane * 8 + i) * PSZ];
#pragma unroll
        for (int o = 16; o > 0; o >>= 1) s += __shfl_down_sync(0xffffffffu, s, o);
        if (lane == 0) scnt = s;
    }
    __syncthreads();

    if (t < 32) {
        const float cntv = scnt;
        const float m = (ssum[0][t] + ssum[1][t] + ssum[2][t] + ssum[3][t]) / cntv;
        g_mean[b * MEANSZ + t * MP + l] = m;           // transposed: [c][l]
        float q = m * m;
#pragma unroll
        for (int o = 16; o > 0; o >>= 1) q += __shfl_down_sync(0xffffffffu, q, o);
        if (t == 0) {
            g_mean[b * MEANSZ + 32 * MP + l]       = q;           // ||m||^2
            g_mean[b * MEANSZ + 32 * MP + 104 + l] = 1.0f / cntv; // 1/cnt
        }
    }
    if (b == 0 && l == 0 && t == 33) out[0] = 0.0f;
}

// ---------------------------------------------------------------------------
// Pass 2: variance via ||f-m||^2 = ||f||^2 - 2 f.m + ||m||^2 (scalar LDS
// gathers from transposed means, 2-wide FMA chains). Blocks 0..127/batch
// stream 2048 px each; block 128 does pairwise-distance + regularizer.
__global__ void __launch_bounds__(512) k_var(const float* __restrict__ in,
                                             const int* __restrict__ tgt,
                                             float* __restrict__ out) {
    __shared__ float sm[MEANSZ];     // 14.1 KB: meansT | msq | invc
    __shared__ float red[16];

    const int b = blockIdx.y;
    for (int i = threadIdx.x; i < MEANSZ; i += 512)
        sm[i] = g_mean[b * MEANSZ + i];
    __syncthreads();
    const float* s_msq  = sm + 32 * MP;
    const float* s_invc = sm + 32 * MP + 104;

    float acc = 0.0f;
    if (blockIdx.x < STREAM) {
        const float* inb = in  + (size_t)b * CC * HW;
        const int*   tb  = tgt + (size_t)b * HW;
        const int p0 = blockIdx.x * 2048 + threadIdx.x;
#pragma unroll
        for (int k = 0; k < 4; ++k) {
            const int p = p0 + k * 512;
            const int l = tb[p];
            const float* fp = inb + p;
            float f2a = 0.0f, f2b = 0.0f, fda = 0.0f, fdb = 0.0f;
#pragma unroll
            for (int c = 0; c < CC; c += 2) {
                const float fa = fp[(size_t)c * HW];
                const float fb = fp[(size_t)(c + 1) * HW];
                const float ma = sm[c * MP + l];
                const float mb = sm[(c + 1) * MP + l];
                f2a = fmaf(fa, fa, f2a);  fda = fmaf(fa, ma, fda);
                f2b = fmaf(fb, fb, f2b);  fdb = fmaf(fb, mb, fdb);
            }
            const float d2 = fmaxf((f2a + f2b) - 2.0f * (fda + fdb) + s_msq[l], 0.0f);
            const float r  = sqrtf(d2);
            const float h  = fmaxf(r - DVAR, 0.0f);
            acc = fmaf(h * h, s_invc[l], acc);
        }
        acc *= (1.0f / (NI * BB));                         // ALPHA = 1
    } else {
        // distance term (9900 ordered pairs) + regularizer
        float accd = 0.0f, accr = 0.0f;
        for (int idx = threadIdx.x; idx < NI * NI; idx += 512) {
            const int i = idx / NI, j = idx - i * NI;
            if (i == j) continue;
            float d2 = 0.0f;
#pragma unroll
            for (int c = 0; c < CC; ++c) {
                const float v = sm[c * MP + i] - sm[c * MP + j];
                d2 = fmaf(v, v, d2);
            }
            const float d = (d2 > 0.0f) ? sqrtf(d2) : 1.0f;
            const float h = fmaxf(REP - d, 0.0f);
            accd = fmaf(h, h, accd);
        }
        if (threadIdx.x < NI) accr = sqrtf(s_msq[threadIdx.x]);
        acc = accd * (1.0f / (NI * (NI - 1) * BB))          // BETA = 1
            + accr * (0.001f / (NI * BB));                  // GAMMA = 0.001
    }

#pragma unroll
    for (int o = 16; o > 0; o >>= 1) acc += __shfl_down_sync(0xffffffffu, acc, o);
    if ((threadIdx.x & 31) == 0) red[threadIdx.x >> 5] = acc;
    __syncthreads();
    if (threadIdx.x < 32) {
        float v = (threadIdx.x < 16) ? red[threadIdx.x] : 0.0f;
#pragma unroll
        for (int o = 8; o > 0; o >>= 1) v += __shfl_down_sync(0xffffffffu, v, o);
        if (threadIdx.x == 0) atomicAdd(out, v);
    }
}

// ---------------------------------------------------------------------------
extern "C" void kernel_launch(void* const* d_in, const int* in_sizes, int n_in,
                              void* d_out, int out_size) {
    const float* in  = (const float*)d_in[0];
    const int*   tgt = (const int*)d_in[1];
    float* out = (float*)d_out;

    dim3 g1(NBLK, BB);
    k_pass1<<<g1, 128>>>(in, tgt);
    dim3 gr(NI, BB);
    k_reduce<<<gr, 160>>>(out);
    dim3 g2(STREAM + 1, BB);
    k_var<<<g2, 512>>>(in, tgt, out);
}

// round 16
// speedup vs baseline: 1.0784x; 1.0784x over previous
#include <cuda_runtime.h>

// ContrastiveLoss (discriminative loss), fixed shapes:
//   input_:  (4, 32, 512, 512) float32, channel-major
//   target:  (4, 1, 512, 512)  int32, labels in [0, 100)
// Output: scalar float32.

#define BB 4
#define CC 32
#define HW 262144
#define NI 100
#define NBLK 256              // pass1 blocks per batch
#define PSZ 3300              // partial: 100*32 sums + 100 counts
#define MEANSZ 3536           // 32*104 meansT + 104 msq + 104 invc
#define MP 104                // transposed means pitch
#define STREAM 128            // k_var streaming blocks per batch
#define TP 36                 // stage tile pitch (px dim), 16B-aligned rows
#define DVAR 0.75f
#define REP 4.0f              // 2 * DELTA_DIST

__device__ float g_part[BB * NBLK * PSZ];   // 13.5 MB raw per-block tables
__device__ float g_mean[BB * MEANSZ];       // meansT + ||m||^2 + 1/cnt

// ---------------------------------------------------------------------------
// Pass 1 (R13, known 42.7us): per-label sums + counts. Conflict-free
// block-shared ATOMS table (T[l*32+lane], lane=channel via broadcast labels
// -> bank=lane). Staging vectorized: tile [c][px] pitch 36, both transpose
// sides are 128-bit ops. Per 32-px chunk/warp: 8 LDG.128 + 8 STS.128 +
// 8 LDS.128 + 32 ATOMS. Grid (256,4), block 128, warp owns 256 px.
// Empirical floor: ~10.5 cyc per warp-ATOMS (atomic unit), ~41us.
__global__ void __launch_bounds__(128) k_pass1(const float* __restrict__ in,
                                               const int* __restrict__ tgt) {
    __shared__ float T[NI * 32];                        // 12.8 KB
    __shared__ float Cn[NI];                            // 400 B
    __shared__ __align__(16) float tile[4][CC * TP];    // 18.4 KB
    __shared__ __align__(16) int   lab[4][32];

    const int b    = blockIdx.y;
    const int tid  = threadIdx.x;
    const int warp = tid >> 5;
    const int lane = tid & 31;
    float* TL = tile[warp];
    int*   L  = lab[warp];

    for (int i = tid; i < NI * 32; i += 128) T[i] = 0.0f;
    if (tid < NI) Cn[tid] = 0.0f;
    __syncthreads();

    const int*   tb  = tgt + (size_t)b * HW;
    const float* inb = in  + (size_t)b * CC * HW;
    const int base = blockIdx.x * 1024 + warp * 256;

    const int cg = lane >> 3;          // channel sub-group 0..3
    const int j4 = 4 * (lane & 7);     // pixel quad 0,4,...,28

    for (int ch = 0; ch < 8; ++ch) {
        const int p0 = base + ch * 32;
        if (lane < 8) ((int4*)L)[lane] = ((const int4*)(tb + p0))[lane];

        // stage: 8 x (LDG.128 + STS.128): 4 channels x 32 px per instr pair
#pragma unroll
        for (int i = 0; i < 8; ++i) {
            const int cc = i * 4 + cg;
            const float4 v = *(const float4*)(inb + (size_t)cc * HW + p0 + j4);
            *(float4*)(TL + cc * TP + j4) = v;
        }
        __syncwarp();

        // counts: one leader atomic per distinct label in this chunk
        {
            const int l = L[lane];
            const unsigned grp = __match_any_sync(0xffffffffu, l);
            if (lane == __ffs(grp) - 1)
                atomicAdd(&Cn[l], (float)__popc(grp));
        }

        // consume: per 4-px group: broadcast label LDS.128 + LDS.128 of
        // 4 px (channel = lane) + 4 conflict-free ATOMS
#pragma unroll
        for (int g = 0; g < 8; ++g) {
            const int4   Lg = *(const int4*)(L + g * 4);
            const float4 v  = *(const float4*)(TL + lane * TP + g * 4);
            atomicAdd(&T[Lg.x * 32 + lane], v.x);
            atomicAdd(&T[Lg.y * 32 + lane], v.y);
            atomicAdd(&T[Lg.z * 32 + lane], v.z);
            atomicAdd(&T[Lg.w * 32 + lane], v.w);
        }
        __syncwarp();
    }
    __syncthreads();

    // flush raw partials (plain coalesced stores, no global atomics)
    float* dst = g_part + (size_t)(b * NBLK + blockIdx.x) * PSZ;
    for (int i = tid; i < NI * 32; i += 128) dst[i] = T[i];
    if (tid < NI) dst[NI * 32 + tid] = Cn[tid];
}

// ---------------------------------------------------------------------------
// Reduce 256 partials/batch -> transposed means + ||m||^2 + 1/cnt.
// Grid (100, 4) [block = one label], 160 threads. Also zeroes out[0].
__global__ void __launch_bounds__(160) k_reduce(float* __restrict__ out) {
    __shared__ float ssum[4][32];
    __shared__ float scnt;

    const int b = blockIdx.y, l = blockIdx.x;
    const int t = threadIdx.x, g = t >> 5, lane = t & 31;
    const float* base = g_part + (size_t)b * NBLK * PSZ;

    if (g < 4) {
        float s = 0.0f;
        const float* p = base + l * 32 + lane;
#pragma unroll 8
        for (int k = g * 64; k < g * 64 + 64; ++k) s += p[(size_t)k * PSZ];
        ssum[g][lane] = s;
    } else {
        float s = 0.0f;
        const float* p = base + NI * 32 + l;
#pragma unroll
        for (int i = 0; i < 8; ++i) s += p[(size_t)(lane * 8 + i) * PSZ];
#pragma unroll
        for (int o = 16; o > 0; o >>= 1) s += __shfl_down_sync(0xffffffffu, s, o);
        if (lane == 0) scnt = s;
    }
    __syncthreads();

    if (t < 32) {
        const float cntv = scnt;
        const float m = (ssum[0][t] + ssum[1][t] + ssum[2][t] + ssum[3][t]) / cntv;
        g_mean[b * MEANSZ + t * MP + l] = m;           // transposed: [c][l]
        float q = m * m;
#pragma unroll
        for (int o = 16; o > 0; o >>= 1) q += __shfl_down_sync(0xffffffffu, q, o);
        if (t == 0) {
            g_mean[b * MEANSZ + 32 * MP + l]       = q;           // ||m||^2
            g_mean[b * MEANSZ + 32 * MP + 104 + l] = 1.0f / cntv; // 1/cnt
        }
    }
    if (b == 0 && l == 0 && t == 33) out[0] = 0.0f;
}

// ---------------------------------------------------------------------------
// Pass 2: variance via ||f-m||^2 = ||f||^2 - 2 f.m + ||m||^2.
// TWO pixels interleaved per thread (p and p+1024): 2 independent gather
// streams + 8 independent FMA streams to cover LDS/LDG latency.
// Blocks 0..127/batch cover 2048 px each; block 128 does pairs + reg term.
__global__ void __launch_bounds__(512) k_var(const float* __restrict__ in,
                                             const int* __restrict__ tgt,
                                             float* __restrict__ out) {
    __shared__ float sm[MEANSZ];     // 14.1 KB: meansT | msq | invc
    __shared__ float red[16];

    const int b = blockIdx.y;
    for (int i = threadIdx.x; i < MEANSZ; i += 512)
        sm[i] = g_mean[b * MEANSZ + i];
    __syncthreads();
    const float* s_msq  = sm + 32 * MP;
    const float* s_invc = sm + 32 * MP + 104;

    float acc = 0.0f;
    if (blockIdx.x < STREAM) {
        const float* inb = in  + (size_t)b * CC * HW;
        const int*   tb  = tgt + (size_t)b * HW;
        const int p0 = blockIdx.x * 2048 + threadIdx.x;
#pragma unroll
        for (int k = 0; k < 2; ++k) {
            const int pA = p0 + k * 512;
            const int pB = pA + 1024;
            const int lA = tb[pA];
            const int lB = tb[pB];
            const float* fpA = inb + pA;
            const float* fpB = inb + pB;
            float f2A0 = 0.0f, f2A1 = 0.0f, fdA0 = 0.0f, fdA1 = 0.0f;
            float f2B0 = 0.0f, f2B1 = 0.0f, fdB0 = 0.0f, fdB1 = 0.0f;
#pragma unroll
            for (int c = 0; c < CC; c += 2) {
                const float fA0 = fpA[(size_t)c * HW];
                const float fA1 = fpA[(size_t)(c + 1) * HW];
                const float fB0 = fpB[(size_t)c * HW];
                const float fB1 = fpB[(size_t)(c + 1) * HW];
                const float mA0 = sm[c * MP + lA];
                const float mA1 = sm[(c + 1) * MP + lA];
                const float mB0 = sm[c * MP + lB];
                const float mB1 = sm[(c + 1) * MP + lB];
                f2A0 = fmaf(fA0, fA0, f2A0);  fdA0 = fmaf(fA0, mA0, fdA0);
                f2A1 = fmaf(fA1, fA1, f2A1);  fdA1 = fmaf(fA1, mA1, fdA1);
                f2B0 = fmaf(fB0, fB0, f2B0);  fdB0 = fmaf(fB0, mB0, fdB0);
                f2B1 = fmaf(fB1, fB1, f2B1);  fdB1 = fmaf(fB1, mB1, fdB1);
            }
            const float d2A = fmaxf((f2A0 + f2A1) - 2.0f * (fdA0 + fdA1) + s_msq[lA], 0.0f);
            const float d2B = fmaxf((f2B0 + f2B1) - 2.0f * (fdB0 + fdB1) + s_msq[lB], 0.0f);
            const float hA  = fmaxf(sqrtf(d2A) - DVAR, 0.0f);
            const float hB  = fmaxf(sqrtf(d2B) - DVAR, 0.0f);
            acc = fmaf(hA * hA, s_invc[lA], acc);
            acc = fmaf(hB * hB, s_invc[lB], acc);
        }
        acc *= (1.0f / (NI * BB));                         // ALPHA = 1
    } else {
        // distance term (9900 ordered pairs) + regularizer
        float accd = 0.0f, accr = 0.0f;
        for (int idx = threadIdx.x; idx < NI * NI; idx += 512) {
            const int i = idx / NI, j = idx - i * NI;
            if (i == j) continue;
            float d2 = 0.0f;
#pragma unroll
            for (int c = 0; c < CC; ++c) {
                const float v = sm[c * MP + i] - sm[c * MP + j];
                d2 = fmaf(v, v, d2);
            }
            const float d = (d2 > 0.0f) ? sqrtf(d2) : 1.0f;
            const float h = fmaxf(REP - d, 0.0f);
            accd = fmaf(h, h, accd);
        }
        if (threadIdx.x < NI) accr = sqrtf(s_msq[threadIdx.x]);
        acc = accd * (1.0f / (NI * (NI - 1) * BB))          // BETA = 1
            + accr * (0.001f / (NI * BB));                  // GAMMA = 0.001
    }

#pragma unroll
    for (int o = 16; o > 0; o >>= 1) acc += __shfl_down_sync(0xffffffffu, acc, o);
    if ((threadIdx.x & 31) == 0) red[threadIdx.x >> 5] = acc;
    __syncthreads();
    if (threadIdx.x < 32) {
        float v = (threadIdx.x < 16) ? red[threadIdx.x] : 0.0f;
#pragma unroll
        for (int o = 8; o > 0; o >>= 1) v += __shfl_down_sync(0xffffffffu, v, o);
        if (threadIdx.x == 0) atomicAdd(out, v);
    }
}

// ---------------------------------------------------------------------------
extern "C" void kernel_launch(void* const* d_in, const int* in_sizes, int n_in,
                              void* d_out, int out_size) {
    const float* in  = (const float*)d_in[0];
    const int*   tgt = (const int*)d_in[1];
    float* out = (float*)d_out;

    dim3 g1(NBLK, BB);
    k_pass1<<<g1, 128>>>(in, tgt);
    dim3 gr(NI, BB);
    k_reduce<<<gr, 160>>>(out);
    dim3 g2(STREAM + 1, BB);
    k_var<<<g2, 512>>>(in, tgt, out);
}